// round 9
// baseline (speedup 1.0000x reference)
#include <cuda_runtime.h>
#include <cstddef>

#define SEQ 4096
#define DIM 1024
#define NHEAD 16
#define HDIM 64

__device__ float g_qkv[(size_t)SEQ * 3 * DIM];   // [T, 3D]
__device__ float g_y[(size_t)SEQ * DIM];         // [T, D]

__device__ __forceinline__ unsigned f2tf(float f) {
    unsigned u;
    asm("cvt.rna.tf32.f32 %0, %1;" : "=r"(u) : "f"(f));
    return u;
}

__device__ __forceinline__ void mma_tf32(float c[4], const unsigned a[4], const unsigned b[2]) {
    asm volatile(
        "mma.sync.aligned.m16n8k8.row.col.f32.tf32.tf32.f32 "
        "{%0,%1,%2,%3}, {%4,%5,%6,%7}, {%8,%9}, {%0,%1,%2,%3};"
        : "+f"(c[0]), "+f"(c[1]), "+f"(c[2]), "+f"(c[3])
        : "r"(a[0]), "r"(a[1]), "r"(a[2]), "r"(a[3]), "r"(b[0]), "r"(b[1]));
}

__device__ __forceinline__ void cp16(void* smem_dst, const void* gsrc) {
    unsigned d = (unsigned)__cvta_generic_to_shared(smem_dst);
    asm volatile("cp.async.cg.shared.global [%0], [%1], 16;" :: "r"(d), "l"(gsrc) : "memory");
}
#define CP_COMMIT() asm volatile("cp.async.commit_group;" ::: "memory")
#define CP_WAIT1()  asm volatile("cp.async.wait_group 1;" ::: "memory")

// ---------------------------------------------------------------------------
// TF32 GEMM "NT": C[m][n] = sum_k A[m][k] * B[n][k]
// 128x128 tile, KT=32, 256 threads (8 warps, 2m x 4n), warp tile 64x32.
// cp.async double-buffered raw-fp32 smem (stride 36); tf32 cvt at frag load.
// Dynamic smem: 4 * 128*36 * 4B = 73728 bytes.
// ---------------------------------------------------------------------------
#define GKT 32
#define GST 36
#define GBUF (128 * GST)

__global__ __launch_bounds__(256) void gemm_tf32_nt(const float* __restrict__ A,
                                                    const float* __restrict__ B,
                                                    float* __restrict__ C,
                                                    int M, int N, int K)
{
    extern __shared__ float sm[];
    float* Asm = sm;               // [2][128][36]
    float* Bsm = sm + 2 * GBUF;    // [2][128][36]

    const int tid  = threadIdx.x;
    const int lane = tid & 31;
    const int warp = tid >> 5;
    const int wm = warp & 1;
    const int wn = warp >> 1;
    const int bm = blockIdx.y * 128;
    const int bn = blockIdx.x * 128;
    const int g = lane >> 2;
    const int r = lane & 3;

    const int srow = tid >> 3;     // 0..31 (then +32 per step)
    const int sc4  = tid & 7;      // 0..7

    auto stage = [&](int kt, int buf) {
        const float* Ap = A + (size_t)bm * K + kt * GKT + sc4 * 4;
        const float* Bp = B + (size_t)bn * K + kt * GKT + sc4 * 4;
        float* Ad = Asm + buf * GBUF;
        float* Bd = Bsm + buf * GBUF;
#pragma unroll
        for (int t = 0; t < 4; ++t) {
            int row = srow + t * 32;
            cp16(&Ad[row * GST + sc4 * 4], Ap + (size_t)row * K);
            cp16(&Bd[row * GST + sc4 * 4], Bp + (size_t)row * K);
        }
    };

    float acc[4][4][4];
#pragma unroll
    for (int mi = 0; mi < 4; ++mi)
#pragma unroll
        for (int nj = 0; nj < 4; ++nj)
#pragma unroll
            for (int e = 0; e < 4; ++e) acc[mi][nj][e] = 0.f;

    const int ntiles = K / GKT;
    stage(0, 0);
    CP_COMMIT();

    for (int kt = 0; kt < ntiles; ++kt) {
        const int buf = kt & 1;
        if (kt + 1 < ntiles) stage(kt + 1, buf ^ 1);
        CP_COMMIT();
        CP_WAIT1();
        __syncthreads();

        const float* Ab = Asm + buf * GBUF;
        const float* Bb = Bsm + buf * GBUF;
#pragma unroll
        for (int kk = 0; kk < 4; ++kk) {
            const int c = kk * 8 + r;
            unsigned af[4][4];
#pragma unroll
            for (int mi = 0; mi < 4; ++mi) {
                int row = wm * 64 + mi * 16 + g;
                af[mi][0] = f2tf(Ab[row * GST + c]);
                af[mi][1] = f2tf(Ab[(row + 8) * GST + c]);
                af[mi][2] = f2tf(Ab[row * GST + c + 4]);
                af[mi][3] = f2tf(Ab[(row + 8) * GST + c + 4]);
            }
            unsigned bf[4][2];
#pragma unroll
            for (int nj = 0; nj < 4; ++nj) {
                int col = wn * 32 + nj * 8 + g;
                bf[nj][0] = f2tf(Bb[col * GST + c]);
                bf[nj][1] = f2tf(Bb[col * GST + c + 4]);
            }
#pragma unroll
            for (int mi = 0; mi < 4; ++mi)
#pragma unroll
                for (int nj = 0; nj < 4; ++nj)
                    mma_tf32(acc[mi][nj], af[mi], bf[nj]);
        }
        __syncthreads();
    }

#pragma unroll
    for (int mi = 0; mi < 4; ++mi) {
        int m = bm + wm * 64 + mi * 16 + g;
#pragma unroll
        for (int nj = 0; nj < 4; ++nj) {
            int n = bn + wn * 32 + nj * 8 + 2 * r;
            *(float2*)&C[(size_t)m * N + n]       = make_float2(acc[mi][nj][0], acc[mi][nj][1]);
            *(float2*)&C[(size_t)(m + 8) * N + n] = make_float2(acc[mi][nj][2], acc[mi][nj][3]);
        }
    }
}

// ---------------------------------------------------------------------------
// TF32 flash attention, causal. Block = (128-query tile, head), 8 warps.
// Each K/V 64-row tile staged once serves 128 queries. Warps fully above the
// diagonal skip compute. Q frags register-resident; P stays in registers.
// ---------------------------------------------------------------------------
__global__ __launch_bounds__(256) void attn_tf32(const float* __restrict__ qkv,
                                                 float* __restrict__ y)
{
    __shared__ unsigned Ks[64][68];
    __shared__ unsigned Vs[64][72];

    const int tid  = threadIdx.x;
    const int lane = tid & 31;
    const int warp = tid >> 5;           // 0..7
    const int qb = gridDim.x - 1 - blockIdx.x;  // heavy blocks first
    const int h  = blockIdx.y;
    const int g = lane >> 2;
    const int r = lane & 3;
    const int row0 = warp * 16;          // 0..112 within 128-query tile
    const float scale = 0.125f;

    // ---- Stage Q (128 rows): rows 0-63 -> Ks, rows 64-127 -> Vs ----
    {
        int row = tid >> 4;              // 0..15 (+16 per step)
        int c4  = tid & 15;
#pragma unroll
        for (int t = 0; t < 8; ++t) {
            int rr = row + t * 16;
            float4 v = *(const float4*)&qkv[(size_t)(qb * 128 + rr) * (3 * DIM) + h * HDIM + c4 * 4];
            uint4 u = make_uint4(f2tf(v.x), f2tf(v.y), f2tf(v.z), f2tf(v.w));
            if (rr < 64) *(uint4*)&Ks[rr][c4 * 4] = u;
            else         *(uint4*)&Vs[rr - 64][c4 * 4] = u;
        }
    }
    __syncthreads();

    unsigned qf[8][4];
    {
        const unsigned* Qs = (warp < 4) ? &Ks[0][0] : &Vs[0][0];
        const int qstride  = (warp < 4) ? 68 : 72;
        const int qr       = (warp < 4) ? row0 : row0 - 64;
#pragma unroll
        for (int kk = 0; kk < 8; ++kk) {
            int c = kk * 8 + r;
            qf[kk][0] = Qs[(qr + g) * qstride + c];
            qf[kk][1] = Qs[(qr + 8 + g) * qstride + c];
            qf[kk][2] = Qs[(qr + g) * qstride + c + 4];
            qf[kk][3] = Qs[(qr + 8 + g) * qstride + c + 4];
        }
    }
    __syncthreads();

    float oacc[8][4];
#pragma unroll
    for (int j = 0; j < 8; ++j)
#pragma unroll
        for (int e = 0; e < 4; ++e) oacc[j][e] = 0.f;

    float m_lo = -1e30f, m_hi = -1e30f, l_lo = 0.f, l_hi = 0.f;

    const int rlo_g = qb * 128 + row0 + g;   // global row (lo half)
    const int ntiles = 2 * qb + 2;

    for (int kt = 0; kt < ntiles; ++kt) {
        // ---- Stage K/V tile (64 rows each) ----
        {
            int row = tid >> 4;          // 0..15 (+16 per step)
            int c4  = tid & 15;
#pragma unroll
            for (int t = 0; t < 4; ++t) {
                int rr = row + t * 16;
                size_t base = (size_t)(kt * 64 + rr) * (3 * DIM) + h * HDIM + c4 * 4;
                float4 kv = *(const float4*)&qkv[base + DIM];
                *(uint4*)&Ks[rr][c4 * 4] = make_uint4(f2tf(kv.x), f2tf(kv.y), f2tf(kv.z), f2tf(kv.w));
                float4 vv = *(const float4*)&qkv[base + 2 * DIM];
                *(uint4*)&Vs[rr][c4 * 4] = make_uint4(f2tf(vv.x), f2tf(vv.y), f2tf(vv.z), f2tf(vv.w));
            }
        }
        __syncthreads();

        // Warp entirely above diagonal? Skip compute.
        if (kt * 64 <= qb * 128 + row0 + 15) {
            // ---- S = Q K^T ----
            float s[8][4];
#pragma unroll
            for (int j = 0; j < 8; ++j)
#pragma unroll
                for (int e = 0; e < 4; ++e) s[j][e] = 0.f;

#pragma unroll
            for (int kk = 0; kk < 8; ++kk) {
                const int c = kk * 8 + r;
                unsigned bK[8][2];
#pragma unroll
                for (int j = 0; j < 8; ++j) {
                    int key = j * 8 + g;
                    bK[j][0] = Ks[key][c];
                    bK[j][1] = Ks[key][c + 4];
                }
#pragma unroll
                for (int j = 0; j < 8; ++j) mma_tf32(s[j], qf[kk], bK[j]);
            }

            // ---- mask + online softmax ----
            const bool needMask = (kt * 64 + 63 > qb * 128 + row0);
            float mx_lo = -1e30f, mx_hi = -1e30f;
#pragma unroll
            for (int j = 0; j < 8; ++j) {
#pragma unroll
                for (int e = 0; e < 2; ++e) {
                    int col = kt * 64 + j * 8 + 2 * r + e;
                    float plo = s[j][e] * scale;
                    float phi = s[j][2 + e] * scale;
                    if (needMask) {
                        if (col > rlo_g)     plo = -1e30f;
                        if (col > rlo_g + 8) phi = -1e30f;
                    }
                    s[j][e] = plo;
                    s[j][2 + e] = phi;
                    mx_lo = fmaxf(mx_lo, plo);
                    mx_hi = fmaxf(mx_hi, phi);
                }
            }
#pragma unroll
            for (int off = 1; off <= 2; off <<= 1) {
                mx_lo = fmaxf(mx_lo, __shfl_xor_sync(0xffffffffu, mx_lo, off));
                mx_hi = fmaxf(mx_hi, __shfl_xor_sync(0xffffffffu, mx_hi, off));
            }
            float mn_lo = fmaxf(m_lo, mx_lo);
            float mn_hi = fmaxf(m_hi, mx_hi);
            float sum_lo = 0.f, sum_hi = 0.f;
#pragma unroll
            for (int j = 0; j < 8; ++j) {
#pragma unroll
                for (int e = 0; e < 2; ++e) {
                    s[j][e]     = __expf(s[j][e] - mn_lo);
                    s[j][2 + e] = __expf(s[j][2 + e] - mn_hi);
                    sum_lo += s[j][e];
                    sum_hi += s[j][2 + e];
                }
            }
#pragma unroll
            for (int off = 1; off <= 2; off <<= 1) {
                sum_lo += __shfl_xor_sync(0xffffffffu, sum_lo, off);
                sum_hi += __shfl_xor_sync(0xffffffffu, sum_hi, off);
            }
            float al_lo = __expf(m_lo - mn_lo);
            float al_hi = __expf(m_hi - mn_hi);
            l_lo = l_lo * al_lo + sum_lo;
            l_hi = l_hi * al_hi + sum_hi;
            m_lo = mn_lo;
            m_hi = mn_hi;
#pragma unroll
            for (int j = 0; j < 8; ++j) {
                oacc[j][0] *= al_lo; oacc[j][1] *= al_lo;
                oacc[j][2] *= al_hi; oacc[j][3] *= al_hi;
            }

            // ---- P to tf32 bits ----
            unsigned pt[8][4];
#pragma unroll
            for (int j = 0; j < 8; ++j)
#pragma unroll
                for (int e = 0; e < 4; ++e) pt[j][e] = f2tf(s[j][e]);

            // ---- O += P V (A-frags via shuffles) ----
            const int srcA = (lane & ~3) | (r >> 1);
            const int srcB = (lane & ~3) | (((r + 4) >> 1));
            const bool odd = (r & 1);
#pragma unroll
            for (int kk = 0; kk < 8; ++kk) {
                unsigned a[4];
                {
                    unsigned t0 = __shfl_sync(0xffffffffu, pt[kk][0], srcA);
                    unsigned t1 = __shfl_sync(0xffffffffu, pt[kk][1], srcA);
                    unsigned t2 = __shfl_sync(0xffffffffu, pt[kk][0], srcB);
                    unsigned t3 = __shfl_sync(0xffffffffu, pt[kk][1], srcB);
                    a[0] = odd ? t1 : t0;
                    a[2] = odd ? t3 : t2;
                    t0 = __shfl_sync(0xffffffffu, pt[kk][2], srcA);
                    t1 = __shfl_sync(0xffffffffu, pt[kk][3], srcA);
                    t2 = __shfl_sync(0xffffffffu, pt[kk][2], srcB);
                    t3 = __shfl_sync(0xffffffffu, pt[kk][3], srcB);
                    a[1] = odd ? t1 : t0;
                    a[3] = odd ? t3 : t2;
                }
#pragma unroll
                for (int j = 0; j < 8; ++j) {
                    unsigned bV[2];
                    bV[0] = Vs[kk * 8 + r][j * 8 + g];
                    bV[1] = Vs[kk * 8 + r + 4][j * 8 + g];
                    mma_tf32(oacc[j], a, bV);
                }
            }
        }
        __syncthreads();
    }

    // ---- normalize + write ----
    float inv_lo = 1.f / l_lo;
    float inv_hi = 1.f / l_hi;
    int row_lo = qb * 128 + row0 + g;
#pragma unroll
    for (int j = 0; j < 8; ++j) {
        int n = h * HDIM + j * 8 + 2 * r;
        *(float2*)&y[(size_t)row_lo * DIM + n] =
            make_float2(oacc[j][0] * inv_lo, oacc[j][1] * inv_lo);
        *(float2*)&y[(size_t)(row_lo + 8) * DIM + n] =
            make_float2(oacc[j][2] * inv_hi, oacc[j][3] * inv_hi);
    }
}

// ---------------------------------------------------------------------------
extern "C" void kernel_launch(void* const* d_in, const int* in_sizes, int n_in,
                              void* d_out, int out_size)
{
    (void)in_sizes; (void)n_in; (void)out_size;
    const float* x      = (const float*)d_in[0];
    const float* w_attn = (const float*)d_in[1];
    const float* w_proj = (const float*)d_in[2];
    float* out = (float*)d_out;

    float* qkv_p = nullptr;
    float* y_p   = nullptr;
    cudaGetSymbolAddress((void**)&qkv_p, g_qkv);
    cudaGetSymbolAddress((void**)&y_p, g_y);

    const int gemm_smem = 4 * GBUF * (int)sizeof(float);   // 73728
    cudaFuncSetAttribute(gemm_tf32_nt, cudaFuncAttributeMaxDynamicSharedMemorySize, gemm_smem);

    {   // QKV: [4096,1024] x [3072,1024]^T
        dim3 grid(3 * DIM / 128, SEQ / 128);
        gemm_tf32_nt<<<grid, 256, gemm_smem>>>(x, w_attn, qkv_p, SEQ, 3 * DIM, DIM);
    }
    {   // causal flash attention, 128-query tiles
        dim3 grid(SEQ / 128, NHEAD);
        attn_tf32<<<grid, 256>>>(qkv_p, y_p);
    }
    {   // proj: [4096,1024] x [1024,1024]^T
        dim3 grid(DIM / 128, SEQ / 128);
        gemm_tf32_nt<<<grid, 256, gemm_smem>>>(y_p, w_proj, out, SEQ, DIM, DIM);
    }
}